// round 2
// baseline (speedup 1.0000x reference)
#include <cuda_runtime.h>
#include <math.h>

#define S_LEN 1024
#define CS 768
#define CZ 128
#define HEADS 24
#define DH 32
#define MAXB 2
#define SS (S_LEN * S_LEN)

// ---------------- scratch ----------------
__device__ float g_emb[MAXB * 3 * CS];
__device__ float g_bsn[MAXB * S_LEN * CS];
__device__ float g_q[MAXB * S_LEN * CS];
__device__ float g_k[MAXB * S_LEN * CS];
__device__ float g_v[MAXB * S_LEN * CS];
__device__ float g_o[MAXB * S_LEN * CS];
__device__ float g_bias[(size_t)HEADS * SS];
__device__ float g_wzp[CZ * HEADS];
__device__ float g_w1[HEADS];
__device__ float g_b0[HEADS];

// fast exp on FMA/ALU pipes (avoids MUFU throughput wall)
__device__ __forceinline__ float fexp(float x) {
    x = fmaxf(fminf(x, 88.0f), -87.0f);
    float y = fmaf(x, 1.4426950408889634f, 12582912.0f);
    int   e = __float_as_int(y) - 0x4B400000;
    float r = y - 12582912.0f;
    float f = fmaf(x, 1.4426950408889634f, -r);
    float p = 1.3333558146e-3f;
    p = fmaf(p, f, 9.6181291076e-3f);
    p = fmaf(p, f, 5.5504108664e-2f);
    p = fmaf(p, f, 2.4022650696e-1f);
    p = fmaf(p, f, 6.9314718056e-1f);
    p = fmaf(p, f, 1.0f);
    return __int_as_float(__float_as_int(p) + (e << 23));
}

// ---------------- prep: fold LN(z) affine into w_z ----------------
__global__ void prep_kernel(const float* __restrict__ lnw,
                            const float* __restrict__ lnb,
                            const float* __restrict__ wz) {
    int t = threadIdx.x;
    for (int i = t; i < CZ * HEADS; i += 256) {
        int c = i / HEADS;
        g_wzp[i] = lnw[c] * wz[i];
    }
    __syncthreads();
    if (t < HEADS) {
        float s1 = 0.f, s0 = 0.f;
        for (int c = 0; c < CZ; c++) {
            s1 += g_wzp[c * HEADS + t];
            s0 += lnb[c] * wz[c * HEADS + t];
        }
        g_w1[t] = s1;
        g_b0[t] = s0;
    }
}

// ---------------- adaLN embedding ----------------
__global__ void adaln_kernel(const float* __restrict__ tin,
                             const float* __restrict__ w,
                             const float* __restrict__ b) {
    __shared__ float st[CS];
    __shared__ float red[256];
    int bb = blockIdx.x;
    int t = threadIdx.x;
    for (int i = t; i < CS; i += 256) {
        float x = tin[bb * CS + i];
        st[i] = x / (1.f + __expf(-x));
    }
    __syncthreads();
    int oo = t & 63, kp = t >> 6;
    int o = blockIdx.y * 64 + oo;
    float acc = 0.f;
    int c0 = kp * 192;
    for (int c = c0; c < c0 + 192; c++) acc += st[c] * w[(size_t)c * (3 * CS) + o];
    red[t] = acc;
    __syncthreads();
    if (t < 64) {
        g_emb[bb * 3 * CS + blockIdx.y * 64 + t] =
            red[t] + red[64 + t] + red[128 + t] + red[192 + t] + b[blockIdx.y * 64 + t];
    }
}

// ---------------- LN(bs)*(1+scale)+shift ----------------
__global__ void bsnorm_kernel(const float* __restrict__ bs) {
    __shared__ float red[8];
    __shared__ float redv[8];
    int row = blockIdx.x;
    int b = row >> 10;
    int t = threadIdx.x;
    const float* x = bs + (size_t)row * CS;
    float x0 = x[t], x1 = x[t + 256], x2 = x[t + 512];
    float s = x0 + x1 + x2;
    #pragma unroll
    for (int o = 16; o; o >>= 1) s += __shfl_xor_sync(0xffffffffu, s, o);
    if ((t & 31) == 0) red[t >> 5] = s;
    __syncthreads();
    float tot = 0.f;
    #pragma unroll
    for (int i = 0; i < 8; i++) tot += red[i];
    float mu = tot * (1.f / CS);
    float d0 = x0 - mu, d1 = x1 - mu, d2 = x2 - mu;
    float q2 = d0 * d0 + d1 * d1 + d2 * d2;
    #pragma unroll
    for (int o = 16; o; o >>= 1) q2 += __shfl_xor_sync(0xffffffffu, q2, o);
    if ((t & 31) == 0) redv[t >> 5] = q2;
    __syncthreads();
    float totv = 0.f;
    #pragma unroll
    for (int i = 0; i < 8; i++) totv += redv[i];
    float rsig = rsqrtf(totv * (1.f / CS) + 1e-5f);
    const float* emb = g_emb + b * 3 * CS;
    float* out = g_bsn + (size_t)row * CS;
    out[t]       = d0 * rsig * (1.f + emb[CS + t])       + emb[t];
    out[t + 256] = d1 * rsig * (1.f + emb[CS + t + 256]) + emb[t + 256];
    out[t + 512] = d2 * rsig * (1.f + emb[CS + t + 512]) + emb[t + 512];
}

// ---------------- fp32 tiled GEMM 128x64, 256 thr ----------------
// MODE 0: C = A@W       MODE 1: C = (A@W + bo) * gate
template <int MODE>
__device__ __forceinline__ void gemm_body(const float* __restrict__ A,
                                          const float* __restrict__ W,
                                          float* __restrict__ C,
                                          const float* __restrict__ bo) {
    __shared__ __align__(16) float As[16][132];
    __shared__ __align__(16) float Ws[16][68];
    int t = threadIdx.x;
    int n0 = blockIdx.x * 64;
    int m0 = blockIdx.y * 128;
    int tx = t & 15, ty = t >> 4;
    float acc[8][4];
    #pragma unroll
    for (int i = 0; i < 8; i++)
        #pragma unroll
        for (int j = 0; j < 4; j++) acc[i][j] = 0.f;

    for (int k0 = 0; k0 < CS; k0 += 16) {
        __syncthreads();
        #pragma unroll
        for (int j = 0; j < 2; j++) {
            int fid = t * 2 + j;
            int lm = fid >> 2, lk = (fid & 3) * 4;
            float4 v = *(const float4*)&A[(size_t)(m0 + lm) * CS + k0 + lk];
            As[lk + 0][lm] = v.x; As[lk + 1][lm] = v.y;
            As[lk + 2][lm] = v.z; As[lk + 3][lm] = v.w;
        }
        {
            int wk = t >> 4, wn = (t & 15) * 4;
            *(float4*)&Ws[wk][wn] = *(const float4*)&W[(size_t)(k0 + wk) * CS + n0 + wn];
        }
        __syncthreads();
        #pragma unroll
        for (int kk = 0; kk < 16; kk++) {
            float a[8], w[4];
            *(float4*)a       = *(float4*)&As[kk][ty * 8];
            *(float4*)(a + 4) = *(float4*)&As[kk][ty * 8 + 4];
            *(float4*)w       = *(float4*)&Ws[kk][tx * 4];
            #pragma unroll
            for (int i = 0; i < 8; i++)
                #pragma unroll
                for (int j = 0; j < 4; j++) acc[i][j] = fmaf(a[i], w[j], acc[i][j]);
        }
    }
    #pragma unroll
    for (int i = 0; i < 8; i++) {
        int m = m0 + ty * 8 + i;
        int n = n0 + tx * 4;
        float4 v;
        if (MODE == 0) {
            v = make_float4(acc[i][0], acc[i][1], acc[i][2], acc[i][3]);
        } else {
            int b = m >> 10;
            float4 g  = *(const float4*)&g_emb[b * 3 * CS + 2 * CS + n];
            float4 bb = *(const float4*)&bo[n];
            v = make_float4((acc[i][0] + bb.x) * g.x, (acc[i][1] + bb.y) * g.y,
                            (acc[i][2] + bb.z) * g.z, (acc[i][3] + bb.w) * g.w);
        }
        *(float4*)&C[(size_t)m * CS + n] = v;
    }
}

__global__ __launch_bounds__(256) void qkv_kernel(const float* __restrict__ Wq,
                                                  const float* __restrict__ Wk,
                                                  const float* __restrict__ Wv) {
    const float* W = (blockIdx.z == 0) ? Wq : (blockIdx.z == 1 ? Wk : Wv);
    float* C = (blockIdx.z == 0) ? g_q : (blockIdx.z == 1 ? g_k : g_v);
    gemm_body<0>(g_bsn, W, C, nullptr);
}

__global__ __launch_bounds__(256) void outproj_kernel(const float* __restrict__ W,
                                                      const float* __restrict__ bo,
                                                      float* __restrict__ out) {
    gemm_body<1>(g_o, W, out, bo);
}

// ---------------- per-head RMS norm q,k in place ----------------
__global__ void rms_kernel(const float* __restrict__ wq,
                           const float* __restrict__ wk, int tot) {
    int gt = blockIdx.x * 256 + threadIdx.x;
    int gw = gt >> 5, lane = gt & 31;
    if (gw >= 2 * tot) return;
    float* buf; const float* w; int idx;
    if (gw < tot) { buf = g_q; w = wq; idx = gw; }
    else          { buf = g_k; w = wk; idx = gw - tot; }
    float x = buf[(size_t)idx * DH + lane];
    float ss = x * x;
    #pragma unroll
    for (int o = 16; o; o >>= 1) ss += __shfl_xor_sync(0xffffffffu, ss, o);
    float r = rsqrtf(ss * (1.f / DH) + 1e-5f);
    buf[(size_t)idx * DH + lane] = x * r * w[lane];
}

// ---------------- bias: LN(z)@w_z folded + mask, (h,i,j) layout ----------------
__global__ __launch_bounds__(256, 4) void bias_kernel(const float* __restrict__ z,
                                                      const int* __restrict__ zmask) {
    __shared__ float zs[64][129];
    __shared__ float ws[128][25];
    __shared__ float smu[64], srs[64];
    int t = threadIdx.x;
    size_t p0 = (size_t)blockIdx.x * 64;

    for (int i = t; i < CZ * HEADS; i += 256) ws[i / HEADS][i % HEADS] = g_wzp[i];
    const float* zp = z + p0 * CZ;
    for (int i = t; i < 64 * CZ; i += 256) zs[i >> 7][i & 127] = zp[i];
    __syncthreads();

    int w = t >> 5, lane = t & 31;
    for (int r = w * 8; r < w * 8 + 8; r++) {
        float a0 = zs[r][lane], a1 = zs[r][lane + 32], a2 = zs[r][lane + 64], a3 = zs[r][lane + 96];
        float s = a0 + a1 + a2 + a3;
        #pragma unroll
        for (int o = 16; o; o >>= 1) s += __shfl_xor_sync(0xffffffffu, s, o);
        float mu = s * (1.f / CZ);
        float d0 = a0 - mu, d1 = a1 - mu, d2 = a2 - mu, d3 = a3 - mu;
        float q = d0 * d0 + d1 * d1 + d2 * d2 + d3 * d3;
        #pragma unroll
        for (int o = 16; o; o >>= 1) q += __shfl_xor_sync(0xffffffffu, q, o);
        if (lane == 0) { smu[r] = mu; srs[r] = rsqrtf(q * (1.f / CZ) + 1e-5f); }
    }
    __syncthreads();

    float acc[4][6];
    int rg = t >> 2, hg = t & 3;
    int r0 = rg * 4, h0 = hg * 6;
    if (t < 64) {
        #pragma unroll
        for (int i = 0; i < 4; i++)
            #pragma unroll
            for (int j = 0; j < 6; j++) acc[i][j] = 0.f;
        for (int c = 0; c < CZ; c++) {
            float a[4], wv[6];
            #pragma unroll
            for (int i = 0; i < 4; i++) a[i] = zs[r0 + i][c];
            #pragma unroll
            for (int j = 0; j < 6; j++) wv[j] = ws[c][h0 + j];
            #pragma unroll
            for (int i = 0; i < 4; i++)
                #pragma unroll
                for (int j = 0; j < 6; j++) acc[i][j] = fmaf(a[i], wv[j], acc[i][j]);
        }
    }
    __syncthreads();
    float* res = &zs[0][0];  // overlay (compute done)
    if (t < 64) {
        #pragma unroll
        for (int i = 0; i < 4; i++) {
            int r = r0 + i;
            float rs = srs[r], mu = smu[r];
            #pragma unroll
            for (int j = 0; j < 6; j++) {
                int h = h0 + j;
                res[r * 24 + h] = rs * acc[i][j] - rs * mu * g_w1[h] + g_b0[h];
            }
        }
    }
    __syncthreads();
    for (int i = t; i < 64 * HEADS; i += 256) {
        int h = i >> 6, lp = i & 63;
        float mb = zmask[p0 + lp] ? 0.f : -1e9f;
        g_bias[(size_t)h * SS + p0 + lp] = res[lp * 24 + h] + mb;
    }
}

// ---------------- flash attention, 1 thread = 1 q row ----------------
#define QT 128
#define JT 32
__global__ __launch_bounds__(128, 3) void attn_kernel(const float* __restrict__ beta) {
    __shared__ __align__(16) float ks[JT][DH + 4];
    __shared__ __align__(16) float vs[JT][DH + 4];
    __shared__ __align__(16) float sb[QT][JT + 4];
    int t = threadIdx.x;
    int h = blockIdx.y % HEADS, b = blockIdx.y / HEADS;
    int q0 = blockIdx.x * QT;
    int q = q0 + t;
    const float* qp = g_q + ((size_t)(b * S_LEN + q)) * CS + h * DH;
    float qr[DH];
    #pragma unroll
    for (int d = 0; d < DH; d++) qr[d] = qp[d] * 0.17677669529663687f;
    float out[DH];
    #pragma unroll
    for (int d = 0; d < DH; d++) out[d] = 0.f;
    float m = -3.0e38f, l = 0.f;
    const float* kbase = g_k + (size_t)(b * S_LEN) * CS + h * DH;
    const float* vbase = g_v + (size_t)(b * S_LEN) * CS + h * DH;
    const float* biasp = g_bias + (size_t)h * SS;
    const float* betap = beta + (size_t)b * SS;

    for (int j0 = 0; j0 < S_LEN; j0 += JT) {
        __syncthreads();
        for (int i = t; i < JT * DH; i += 128) {
            int r = i >> 5, d = i & 31;
            ks[r][d] = kbase[(size_t)(j0 + r) * CS + d];
            vs[r][d] = vbase[(size_t)(j0 + r) * CS + d];
        }
        for (int i = t; i < QT * JT; i += 128) {
            int il = i >> 5, jj = i & 31;
            size_t off = (size_t)(q0 + il) * S_LEN + j0 + jj;
            sb[il][jj] = biasp[off] + betap[off];
        }
        __syncthreads();

        float s[JT];
        #pragma unroll
        for (int jj = 0; jj < JT; jj++) {
            float acc = 0.f;
            #pragma unroll
            for (int d = 0; d < DH; d += 4) {
                float4 kv = *(const float4*)&ks[jj][d];
                acc = fmaf(qr[d], kv.x, acc);
                acc = fmaf(qr[d + 1], kv.y, acc);
                acc = fmaf(qr[d + 2], kv.z, acc);
                acc = fmaf(qr[d + 3], kv.w, acc);
            }
            s[jj] = acc;
        }
        #pragma unroll
        for (int jj = 0; jj < JT; jj += 4) {
            float4 bv = *(const float4*)&sb[t][jj];
            s[jj] += bv.x; s[jj + 1] += bv.y; s[jj + 2] += bv.z; s[jj + 3] += bv.w;
        }
        float tmax = s[0];
        #pragma unroll
        for (int jj = 1; jj < JT; jj++) tmax = fmaxf(tmax, s[jj]);
        float mnew = fmaxf(m, tmax);
        float corr = fexp(m - mnew);
        l *= corr;
        #pragma unroll
        for (int d = 0; d < DH; d++) out[d] *= corr;
        #pragma unroll
        for (int jj = 0; jj < JT; jj++) {
            float p = fexp(s[jj] - mnew);
            l += p;
            #pragma unroll
            for (int d = 0; d < DH; d += 4) {
                float4 vv = *(const float4*)&vs[jj][d];
                out[d]     = fmaf(p, vv.x, out[d]);
                out[d + 1] = fmaf(p, vv.y, out[d + 1]);
                out[d + 2] = fmaf(p, vv.z, out[d + 2]);
                out[d + 3] = fmaf(p, vv.w, out[d + 3]);
            }
        }
        m = mnew;
    }
    float inv = 1.f / l;
    float* op = g_o + ((size_t)(b * S_LEN + q)) * CS + h * DH;
    #pragma unroll
    for (int d = 0; d < DH; d++) op[d] = out[d] * inv;
}

// ---------------- launch ----------------
extern "C" void kernel_launch(void* const* d_in, const int* in_sizes, int n_in,
                              void* d_out, int out_size) {
    const float* bs      = (const float*)d_in[0];
    const float* z       = (const float*)d_in[1];
    const float* tt      = (const float*)d_in[2];
    const float* beta    = (const float*)d_in[3];
    const int*   z_mask  = (const int*)d_in[4];
    const float* w_adaln = (const float*)d_in[5];
    const float* b_adaln = (const float*)d_in[6];
    const float* ln_z_w  = (const float*)d_in[7];
    const float* ln_z_b  = (const float*)d_in[8];
    const float* w_q     = (const float*)d_in[9];
    const float* w_k     = (const float*)d_in[10];
    const float* w_v     = (const float*)d_in[11];
    const float* w_z     = (const float*)d_in[12];
    const float* rms_q_w = (const float*)d_in[13];
    const float* rms_k_w = (const float*)d_in[14];
    const float* w_o     = (const float*)d_in[15];
    const float* b_o     = (const float*)d_in[16];
    float* out = (float*)d_out;

    int B = in_sizes[0] / (S_LEN * CS);

    prep_kernel<<<1, 256>>>(ln_z_w, ln_z_b, w_z);
    adaln_kernel<<<dim3(B, 3 * CS / 64), 256>>>(tt, w_adaln, b_adaln);
    bsnorm_kernel<<<B * S_LEN, 256>>>(bs);
    qkv_kernel<<<dim3(CS / 64, B * S_LEN / 128, 3), 256>>>(w_q, w_k, w_v);
    rms_kernel<<<(2 * B * S_LEN * HEADS * 32 + 255) / 256, 256>>>(rms_q_w, rms_k_w, B * S_LEN * HEADS);
    bias_kernel<<<SS / 64, 256>>>(z, z_mask);
    attn_kernel<<<dim3(S_LEN / QT, B * HEADS), 128>>>(beta);
    outproj_kernel<<<dim3(CS / 64, B * S_LEN / 128), 256>>>(w_o, b_o, out);
}

// round 8
// speedup vs baseline: 2.2445x; 2.2445x over previous
#include <cuda_runtime.h>
#include <math.h>

#define S_LEN 1024
#define CS 768
#define CZ 128
#define HEADS 24
#define DH 32
#define MAXB 2
#define SS (S_LEN * S_LEN)

// ---------------- scratch ----------------
__device__ float g_emb[MAXB * 3 * CS];
__device__ float g_bsn[MAXB * S_LEN * CS];
__device__ float g_q[MAXB * S_LEN * CS];
__device__ float g_k[MAXB * S_LEN * CS];
__device__ float g_v[MAXB * S_LEN * CS];
__device__ float g_o[MAXB * S_LEN * CS];      // (b, s, h*32+d) row-major CS
__device__ float g_bias[(size_t)HEADS * SS];
__device__ float g_wzp[CZ * HEADS];
__device__ float g_w1[HEADS];
__device__ float g_b0[HEADS];

// fast exp on FMA/ALU pipes (avoids MUFU throughput wall)
__device__ __forceinline__ float fexp(float x) {
    x = fmaxf(fminf(x, 88.0f), -87.0f);
    float y = fmaf(x, 1.4426950408889634f, 12582912.0f);
    int   e = __float_as_int(y) - 0x4B400000;
    float r = y - 12582912.0f;
    float f = fmaf(x, 1.4426950408889634f, -r);
    float p = 1.3333558146e-3f;
    p = fmaf(p, f, 9.6181291076e-3f);
    p = fmaf(p, f, 5.5504108664e-2f);
    p = fmaf(p, f, 2.4022650696e-1f);
    p = fmaf(p, f, 6.9314718056e-1f);
    p = fmaf(p, f, 1.0f);
    return __int_as_float(__float_as_int(p) + (e << 23));
}

// ---------------- tf32 helpers ----------------
__device__ __forceinline__ unsigned cvt_tf32(float x) {
    unsigned r;
    asm("cvt.rna.tf32.f32 %0, %1;" : "=r"(r) : "f"(x));
    return r;
}
__device__ __forceinline__ void mma_tf32(float c[4], const unsigned a[4], const unsigned b[2]) {
    asm volatile("mma.sync.aligned.m16n8k8.row.col.f32.tf32.tf32.f32 "
                 "{%0,%1,%2,%3}, {%4,%5,%6,%7}, {%8,%9}, {%0,%1,%2,%3};"
                 : "+f"(c[0]), "+f"(c[1]), "+f"(c[2]), "+f"(c[3])
                 : "r"(a[0]), "r"(a[1]), "r"(a[2]), "r"(a[3]), "r"(b[0]), "r"(b[1]));
}

// ---------------- prep: fold LN(z) affine into w_z ----------------
__global__ void prep_kernel(const float* __restrict__ lnw,
                            const float* __restrict__ lnb,
                            const float* __restrict__ wz) {
    int t = threadIdx.x;
    for (int i = t; i < CZ * HEADS; i += 256) {
        int c = i / HEADS;
        g_wzp[i] = lnw[c] * wz[i];
    }
    __syncthreads();
    if (t < HEADS) {
        float s1 = 0.f, s0 = 0.f;
        for (int c = 0; c < CZ; c++) {
            s1 += g_wzp[c * HEADS + t];
            s0 += lnb[c] * wz[c * HEADS + t];
        }
        g_w1[t] = s1;
        g_b0[t] = s0;
    }
}

// ---------------- adaLN embedding ----------------
__global__ void adaln_kernel(const float* __restrict__ tin,
                             const float* __restrict__ w,
                             const float* __restrict__ b) {
    __shared__ float st[CS];
    __shared__ float red[256];
    int bb = blockIdx.x;
    int t = threadIdx.x;
    for (int i = t; i < CS; i += 256) {
        float x = tin[bb * CS + i];
        st[i] = x / (1.f + __expf(-x));
    }
    __syncthreads();
    int oo = t & 63, kp = t >> 6;
    int o = blockIdx.y * 64 + oo;
    float acc = 0.f;
    int c0 = kp * 192;
    for (int c = c0; c < c0 + 192; c++) acc += st[c] * w[(size_t)c * (3 * CS) + o];
    red[t] = acc;
    __syncthreads();
    if (t < 64) {
        g_emb[bb * 3 * CS + blockIdx.y * 64 + t] =
            red[t] + red[64 + t] + red[128 + t] + red[192 + t] + b[blockIdx.y * 64 + t];
    }
}

// ---------------- LN(bs)*(1+scale)+shift ----------------
__global__ void bsnorm_kernel(const float* __restrict__ bs) {
    __shared__ float red[8];
    __shared__ float redv[8];
    int row = blockIdx.x;
    int b = row >> 10;
    int t = threadIdx.x;
    const float* x = bs + (size_t)row * CS;
    float x0 = x[t], x1 = x[t + 256], x2 = x[t + 512];
    float s = x0 + x1 + x2;
    #pragma unroll
    for (int o = 16; o; o >>= 1) s += __shfl_xor_sync(0xffffffffu, s, o);
    if ((t & 31) == 0) red[t >> 5] = s;
    __syncthreads();
    float tot = 0.f;
    #pragma unroll
    for (int i = 0; i < 8; i++) tot += red[i];
    float mu = tot * (1.f / CS);
    float d0 = x0 - mu, d1 = x1 - mu, d2 = x2 - mu;
    float q2 = d0 * d0 + d1 * d1 + d2 * d2;
    #pragma unroll
    for (int o = 16; o; o >>= 1) q2 += __shfl_xor_sync(0xffffffffu, q2, o);
    if ((t & 31) == 0) redv[t >> 5] = q2;
    __syncthreads();
    float totv = 0.f;
    #pragma unroll
    for (int i = 0; i < 8; i++) totv += redv[i];
    float rsig = rsqrtf(totv * (1.f / CS) + 1e-5f);
    const float* emb = g_emb + b * 3 * CS;
    float* out = g_bsn + (size_t)row * CS;
    out[t]       = d0 * rsig * (1.f + emb[CS + t])       + emb[t];
    out[t + 256] = d1 * rsig * (1.f + emb[CS + t + 256]) + emb[t + 256];
    out[t + 512] = d2 * rsig * (1.f + emb[CS + t + 512]) + emb[t + 512];
}

// ---------------- per-head RMS norm q,k in place ----------------
__global__ void rms_kernel(const float* __restrict__ wq,
                           const float* __restrict__ wk, int tot) {
    int gt = blockIdx.x * 256 + threadIdx.x;
    int gw = gt >> 5, lane = gt & 31;
    if (gw >= 2 * tot) return;
    float* buf; const float* w; int idx;
    if (gw < tot) { buf = g_q; w = wq; idx = gw; }
    else          { buf = g_k; w = wk; idx = gw - tot; }
    float x = buf[(size_t)idx * DH + lane];
    float ss = x * x;
    #pragma unroll
    for (int o = 16; o; o >>= 1) ss += __shfl_xor_sync(0xffffffffu, ss, o);
    float r = rsqrtf(ss * (1.f / DH) + 1e-5f);
    buf[(size_t)idx * DH + lane] = x * r * w[lane];
}

// ================= TF32 MMA GEMM: CTA 128x128, 8 warps (2x4), warp 64x32 =====
// MODE 0: C = A@W       MODE 1: C = (A@W + bo) * gate
template <int MODE>
__device__ __forceinline__ void gemm_mma_body(const float* __restrict__ A,
                                              const float* __restrict__ W,
                                              float* __restrict__ C,
                                              const float* __restrict__ bo) {
    __shared__ __align__(16) float As[128][36];   // A-frag: stride%32==4 -> conflict-free
    __shared__ __align__(16) float Bs[32][136];   // 32k x 128n (+8 pad; 136%32==8 -> conflict-free)
    int t = threadIdx.x;
    int warp = t >> 5, lane = t & 31;
    int g = lane >> 2, tig = lane & 3;
    int wm = warp >> 2, wn = warp & 3;           // 2 x 4 warp grid
    int n0 = blockIdx.x * 128;
    int m0 = blockIdx.y * 128;

    float c[4][4][4];                            // [m-atom][n-atom][frag]
    #pragma unroll
    for (int i = 0; i < 4; i++)
        #pragma unroll
        for (int j = 0; j < 4; j++)
            #pragma unroll
            for (int k = 0; k < 4; k++) c[i][j][k] = 0.f;

    for (int k0 = 0; k0 < CS; k0 += 32) {
        __syncthreads();
        #pragma unroll
        for (int i = 0; i < 4; i++) {
            int idx = t + i * 256;
            int row = idx >> 3, c4 = idx & 7;
            float4 v = *(const float4*)&A[(size_t)(m0 + row) * CS + k0 + c4 * 4];
            float4 cv = make_float4(__uint_as_float(cvt_tf32(v.x)), __uint_as_float(cvt_tf32(v.y)),
                                    __uint_as_float(cvt_tf32(v.z)), __uint_as_float(cvt_tf32(v.w)));
            *(float4*)&As[row][c4 * 4] = cv;
        }
        #pragma unroll
        for (int i = 0; i < 4; i++) {
            int idx = t + i * 256;
            int row = idx >> 5, c4 = idx & 31;
            float4 v = *(const float4*)&W[(size_t)(k0 + row) * CS + n0 + c4 * 4];
            float4 cv = make_float4(__uint_as_float(cvt_tf32(v.x)), __uint_as_float(cvt_tf32(v.y)),
                                    __uint_as_float(cvt_tf32(v.z)), __uint_as_float(cvt_tf32(v.w)));
            *(float4*)&Bs[row][c4 * 4] = cv;
        }
        __syncthreads();
        #pragma unroll
        for (int kk = 0; kk < 4; kk++) {
            unsigned a[4][4], b[4][2];
            #pragma unroll
            for (int ma = 0; ma < 4; ma++) {
                int r = wm * 64 + ma * 16 + g;
                a[ma][0] = __float_as_uint(As[r][kk * 8 + tig]);
                a[ma][1] = __float_as_uint(As[r + 8][kk * 8 + tig]);
                a[ma][2] = __float_as_uint(As[r][kk * 8 + tig + 4]);
                a[ma][3] = __float_as_uint(As[r + 8][kk * 8 + tig + 4]);
            }
            #pragma unroll
            for (int na = 0; na < 4; na++) {
                int cc = wn * 32 + na * 8 + g;
                b[na][0] = __float_as_uint(Bs[kk * 8 + tig][cc]);
                b[na][1] = __float_as_uint(Bs[kk * 8 + tig + 4][cc]);
            }
            #pragma unroll
            for (int ma = 0; ma < 4; ma++)
                #pragma unroll
                for (int na = 0; na < 4; na++) mma_tf32(c[ma][na], a[ma], b[na]);
        }
    }
    // epilogue
    #pragma unroll
    for (int ma = 0; ma < 4; ma++) {
        int r = m0 + wm * 64 + ma * 16 + g;
        #pragma unroll
        for (int na = 0; na < 4; na++) {
            int n = n0 + wn * 32 + na * 8 + 2 * tig;
            if (MODE == 0) {
                *(float2*)&C[(size_t)r * CS + n]       = make_float2(c[ma][na][0], c[ma][na][1]);
                *(float2*)&C[(size_t)(r + 8) * CS + n] = make_float2(c[ma][na][2], c[ma][na][3]);
            } else {
                int b1 = r >> 10, b2 = (r + 8) >> 10;
                float2 bb = *(const float2*)&bo[n];
                float2 g1 = *(const float2*)&g_emb[b1 * 3 * CS + 2 * CS + n];
                float2 g2 = *(const float2*)&g_emb[b2 * 3 * CS + 2 * CS + n];
                *(float2*)&C[(size_t)r * CS + n] =
                    make_float2((c[ma][na][0] + bb.x) * g1.x, (c[ma][na][1] + bb.y) * g1.y);
                *(float2*)&C[(size_t)(r + 8) * CS + n] =
                    make_float2((c[ma][na][2] + bb.x) * g2.x, (c[ma][na][3] + bb.y) * g2.y);
            }
        }
    }
}

__global__ __launch_bounds__(256) void qkv_kernel(const float* __restrict__ Wq,
                                                  const float* __restrict__ Wk,
                                                  const float* __restrict__ Wv) {
    const float* W = (blockIdx.z == 0) ? Wq : (blockIdx.z == 1 ? Wk : Wv);
    float* C = (blockIdx.z == 0) ? g_q : (blockIdx.z == 1 ? g_k : g_v);
    gemm_mma_body<0>(g_bsn, W, C, nullptr);
}

__global__ __launch_bounds__(256) void outproj_kernel(const float* __restrict__ W,
                                                      const float* __restrict__ bo,
                                                      float* __restrict__ out) {
    gemm_mma_body<1>(g_o, W, out, bo);
}

// ================= bias: LN(z)@w_z folded + mask via TF32 MMA =================
// 64 pixel-rows per CTA, 128 threads (4 warps x 16 rows), K=128, N=24 (3 atoms)
__global__ __launch_bounds__(128) void bias_kernel(const float* __restrict__ z,
                                                   const int* __restrict__ zmask) {
    __shared__ __align__(16) float zs[64][132];   // raw z tile; A-frag stride%32==4
    __shared__ __align__(16) float ws[CZ * HEADS]; // tf32 w'; flat [k*24+n]
    __shared__ float smu[64], srs[64];
    int t = threadIdx.x;
    int warp = t >> 5, lane = t & 31;
    int g = lane >> 2, tig = lane & 3;
    int m0 = warp * 16;
    size_t p0 = (size_t)blockIdx.x * 64;

    #pragma unroll
    for (int i = 0; i < 6; i++) {
        int idx = t + i * 128;
        float4 v = *(const float4*)&g_wzp[idx * 4];
        float4 cv = make_float4(__uint_as_float(cvt_tf32(v.x)), __uint_as_float(cvt_tf32(v.y)),
                                __uint_as_float(cvt_tf32(v.z)), __uint_as_float(cvt_tf32(v.w)));
        *(float4*)&ws[idx * 4] = cv;
    }
    const float* zp = z + p0 * CZ;
    #pragma unroll
    for (int i = 0; i < 16; i++) {
        int idx = t + i * 128;
        int row = idx >> 5, c4 = idx & 31;
        *(float4*)&zs[row][c4 * 4] = *(const float4*)&zp[row * CZ + c4 * 4];
    }
    __syncthreads();

    // row stats (each warp its own 16 rows)
    for (int r = m0; r < m0 + 16; r++) {
        float a0 = zs[r][lane], a1 = zs[r][lane + 32], a2 = zs[r][lane + 64], a3 = zs[r][lane + 96];
        float s = a0 + a1 + a2 + a3;
        #pragma unroll
        for (int o = 16; o; o >>= 1) s += __shfl_xor_sync(0xffffffffu, s, o);
        float mu = s * (1.f / CZ);
        float d0 = a0 - mu, d1 = a1 - mu, d2 = a2 - mu, d3 = a3 - mu;
        float q = d0 * d0 + d1 * d1 + d2 * d2 + d3 * d3;
        #pragma unroll
        for (int o = 16; o; o >>= 1) q += __shfl_xor_sync(0xffffffffu, q, o);
        if (lane == 0) { smu[r] = mu; srs[r] = rsqrtf(q * (1.f / CZ) + 1e-5f); }
    }
    __syncwarp();

    float c[3][4];
    #pragma unroll
    for (int na = 0; na < 3; na++)
        #pragma unroll
        for (int k = 0; k < 4; k++) c[na][k] = 0.f;

    #pragma unroll
    for (int ks = 0; ks < 16; ks++) {
        unsigned a[4], b[3][2];
        a[0] = cvt_tf32(zs[m0 + g][ks * 8 + tig]);
        a[1] = cvt_tf32(zs[m0 + g + 8][ks * 8 + tig]);
        a[2] = cvt_tf32(zs[m0 + g][ks * 8 + tig + 4]);
        a[3] = cvt_tf32(zs[m0 + g + 8][ks * 8 + tig + 4]);
        #pragma unroll
        for (int na = 0; na < 3; na++) {
            b[na][0] = __float_as_uint(ws[(ks * 8 + tig) * HEADS + na * 8 + g]);
            b[na][1] = __float_as_uint(ws[(ks * 8 + tig + 4) * HEADS + na * 8 + g]);
        }
        #pragma unroll
        for (int na = 0; na < 3; na++) mma_tf32(c[na], a, b[na]);
    }
    __syncthreads();   // all mma reads of zs done before overlay

    float* res = &zs[0][0];  // 64x24 overlay
    #pragma unroll
    for (int na = 0; na < 3; na++) {
        int col = na * 8 + 2 * tig;
        int r1 = m0 + g, r2 = m0 + g + 8;
        float w10 = g_w1[col], w11 = g_w1[col + 1];
        float b00 = g_b0[col], b01 = g_b0[col + 1];
        res[r1 * 24 + col]     = srs[r1] * c[na][0] - srs[r1] * smu[r1] * w10 + b00;
        res[r1 * 24 + col + 1] = srs[r1] * c[na][1] - srs[r1] * smu[r1] * w11 + b01;
        res[r2 * 24 + col]     = srs[r2] * c[na][2] - srs[r2] * smu[r2] * w10 + b00;
        res[r2 * 24 + col + 1] = srs[r2] * c[na][3] - srs[r2] * smu[r2] * w11 + b01;
    }
    __syncthreads();
    for (int i = t; i < 64 * HEADS; i += 128) {
        int h = i >> 6, lp = i & 63;
        float mb = zmask[p0 + lp] ? 0.f : -1e9f;
        g_bias[(size_t)h * SS + p0 + lp] = res[lp * 24 + h] + mb;
    }
}

// ================= flash attention, TF32 MMA =================
// CTA: 128 q-rows, 8 warps (16 rows each), j-tiles of 32
#define QT 128
#define JT 32
__global__ __launch_bounds__(256) void attn_kernel(const float* __restrict__ beta) {
    __shared__ __align__(16) float ks_s[JT][36];   // B-frag (rows=g): stride%32==4
    __shared__ __align__(16) float vs_s[JT][40];   // B-frag (rows=tig): stride%32==8
    __shared__ __align__(16) float ps[QT][36];     // bias stage + P; A-frag stride%32==4
    int t = threadIdx.x;
    int warp = t >> 5, lane = t & 31;
    int g = lane >> 2, tig = lane & 3;
    int m0 = warp * 16;
    int h = blockIdx.y % HEADS, b = blockIdx.y / HEADS;
    int q0 = blockIdx.x * QT;

    // Q fragments (scaled + tf32)
    unsigned qa[4][4];
    {
        const float* qp = g_q + ((size_t)(b * S_LEN + q0 + m0)) * CS + h * DH;
        const float sc = 0.17677669529663687f;
        #pragma unroll
        for (int ksx = 0; ksx < 4; ksx++) {
            qa[ksx][0] = cvt_tf32(qp[(size_t)g * CS + ksx * 8 + tig] * sc);
            qa[ksx][1] = cvt_tf32(qp[(size_t)(g + 8) * CS + ksx * 8 + tig] * sc);
            qa[ksx][2] = cvt_tf32(qp[(size_t)g * CS + ksx * 8 + tig + 4] * sc);
            qa[ksx][3] = cvt_tf32(qp[(size_t)(g + 8) * CS + ksx * 8 + tig + 4] * sc);
        }
    }
    float ov[4][4];
    #pragma unroll
    for (int i = 0; i < 4; i++)
        #pragma unroll
        for (int j = 0; j < 4; j++) ov[i][j] = 0.f;
    float mrow[2] = {-3.0e38f, -3.0e38f};
    float lrow[2] = {0.f, 0.f};

    const float* kbase = g_k + (size_t)(b * S_LEN) * CS + h * DH;
    const float* vbase = g_v + (size_t)(b * S_LEN) * CS + h * DH;
    const float* biasp = g_bias + (size_t)h * SS;
    const float* betap = beta + (size_t)b * SS;

    for (int j0 = 0; j0 < S_LEN; j0 += JT) {
        __syncthreads();
        {   // K/V tiles (tf32)
            int row = t >> 3, c4 = t & 7;
            float4 kv = *(const float4*)&kbase[(size_t)(j0 + row) * CS + c4 * 4];
            float4 vv = *(const float4*)&vbase[(size_t)(j0 + row) * CS + c4 * 4];
            *(float4*)&ks_s[row][c4 * 4] =
                make_float4(__uint_as_float(cvt_tf32(kv.x)), __uint_as_float(cvt_tf32(kv.y)),
                            __uint_as_float(cvt_tf32(kv.z)), __uint_as_float(cvt_tf32(kv.w)));
            *(float4*)&vs_s[row][c4 * 4] =
                make_float4(__uint_as_float(cvt_tf32(vv.x)), __uint_as_float(cvt_tf32(vv.y)),
                            __uint_as_float(cvt_tf32(vv.z)), __uint_as_float(cvt_tf32(vv.w)));
        }
        #pragma unroll
        for (int i = 0; i < 4; i++) {   // bias + beta -> ps
            int idx = t + i * 256;
            int row = idx >> 3, c4 = idx & 7;
            size_t off = (size_t)(q0 + row) * S_LEN + j0 + c4 * 4;
            float4 bv = *(const float4*)&biasp[off];
            float4 tv = *(const float4*)&betap[off];
            *(float4*)&ps[row][c4 * 4] =
                make_float4(bv.x + tv.x, bv.y + tv.y, bv.z + tv.z, bv.w + tv.w);
        }
        __syncthreads();

        // scores: c init = bias, then += QK^T
        float c[4][4];
        #pragma unroll
        for (int a = 0; a < 4; a++) {
            float2 v1 = *(const float2*)&ps[m0 + g][a * 8 + 2 * tig];
            float2 v2 = *(const float2*)&ps[m0 + g + 8][a * 8 + 2 * tig];
            c[a][0] = v1.x; c[a][1] = v1.y; c[a][2] = v2.x; c[a][3] = v2.y;
        }
        #pragma unroll
        for (int ksx = 0; ksx < 4; ksx++) {
            #pragma unroll
            for (int a = 0; a < 4; a++) {
                unsigned bf[2];
                bf[0] = __float_as_uint(ks_s[a * 8 + g][ksx * 8 + tig]);
                bf[1] = __float_as_uint(ks_s[a * 8 + g][ksx * 8 + tig + 4]);
                mma_tf32(c[a], qa[ksx], bf);
            }
        }

        // online softmax per row (g and g+8), write P -> ps
        #pragma unroll
        for (int r = 0; r < 2; r++) {
            float mx = c[0][2 * r];
            #pragma unroll
            for (int a = 0; a < 4; a++) mx = fmaxf(mx, fmaxf(c[a][2 * r], c[a][2 * r + 1]));
            mx = fmaxf(mx, __shfl_xor_sync(0xffffffffu, mx, 1));
            mx = fmaxf(mx, __shfl_xor_sync(0xffffffffu, mx, 2));
            float mn = fmaxf(mrow[r], mx);
            float corr = fexp(mrow[r] - mn);
            mrow[r] = mn;
            lrow[r] *= corr;
            #pragma unroll
            for (int od = 0; od < 4; od++) { ov[od][2 * r] *= corr; ov[od][2 * r + 1] *= corr; }
            float sum = 0.f;
            int rr = m0 + g + 8 * r;
            #pragma unroll
            for (int a = 0; a < 4; a++) {
                float pp0 = fexp(c[a][2 * r] - mn);
                float pp1 = fexp(c[a][2 * r + 1] - mn);
                sum += pp0 + pp1;
                *(float2*)&ps[rr][a * 8 + 2 * tig] =
                    make_float2(__uint_as_float(cvt_tf32(pp0)), __uint_as_float(cvt_tf32(pp1)));
            }
            sum += __shfl_xor_sync(0xffffffffu, sum, 1);
            sum += __shfl_xor_sync(0xffffffffu, sum, 2);
            lrow[r] += sum;
        }
        __syncwarp();

        // out += P @ V
        #pragma unroll
        for (int ksx = 0; ksx < 4; ksx++) {
            unsigned pa[4];
            pa[0] = __float_as_uint(ps[m0 + g][ksx * 8 + tig]);
            pa[1] = __float_as_uint(ps[m0 + g + 8][ksx * 8 + tig]);
            pa[2] = __float_as_uint(ps[m0 + g][ksx * 8 + tig + 4]);
            pa[3] = __float_as_uint(ps[m0 + g + 8][ksx * 8 + tig + 4]);
            #pragma unroll
            for (int od = 0; od < 4; od++) {
                unsigned bf[2];
                bf[0] = __float_as_uint(vs_s[ksx * 8 + tig][od * 8 + g]);
                bf[1] = __float_as_uint(vs_s[ksx * 8 + tig + 4][od * 8 + g]);
                mma_tf32(ov[od], pa, bf);
            }
        }
    }

    // epilogue: normalize, write (b, q, h*32+d)
    float inv0 = 1.f / lrow[0], inv1 = 1.f / lrow[1];
    float* op = g_o + ((size_t)(b * S_LEN + q0 + m0)) * CS + h * DH;
    #pragma unroll
    for (int od = 0; od < 4; od++) {
        int d = od * 8 + 2 * tig;
        *(float2*)&op[(size_t)g * CS + d]       = make_float2(ov[od][0] * inv0, ov[od][1] * inv0);
        *(float2*)&op[(size_t)(g + 8) * CS + d] = make_float2(ov[od][2] * inv1, ov[od][3] * inv1);
    }
}

// ---------------- launch ----------------
extern "C" void kernel_launch(void* const* d_in, const int* in_sizes, int n_in,
                              void* d_out, int out_size) {
    const float* bs      = (const float*)d_in[0];
    const float* z       = (const float*)d_in[1];
    const float* tt      = (const float*)d_in[2];
    const float* beta    = (const float*)d_in[3];
    const int*   z_mask  = (const int*)d_in[4];
    const float* w_adaln = (const float*)d_in[5];
    const float* b_adaln = (const float*)d_in[6];
    const float* ln_z_w  = (const float*)d_in[7];
    const float* ln_z_b  = (const float*)d_in[8];
    const float* w_q     = (const float*)d_in[9];
    const float* w_k     = (const float*)d_in[10];
    const float* w_v     = (const float*)d_in[11];
    const float* w_z     = (const float*)d_in[12];
    const float* rms_q_w = (const float*)d_in[13];
    const float* rms_k_w = (const float*)d_in[14];
    const float* w_o     = (const float*)d_in[15];
    const float* b_o     = (const float*)d_in[16];
    float* out = (float*)d_out;

    int B = in_sizes[0] / (S_LEN * CS);

    prep_kernel<<<1, 256>>>(ln_z_w, ln_z_b, w_z);
    adaln_kernel<<<dim3(B, 3 * CS / 64), 256>>>(tt, w_adaln, b_adaln);
    bsnorm_kernel<<<B * S_LEN, 256>>>(bs);
    qkv_kernel<<<dim3(CS / 128, B * S_LEN / 128, 3), 256>>>(w_q, w_k, w_v);
    rms_kernel<<<(2 * B * S_LEN * HEADS * 32 + 255) / 256, 256>>>(rms_q_w, rms_k_w, B * S_LEN * HEADS);
    bias_kernel<<<SS / 64, 128>>>(z, z_mask);
    attn_kernel<<<dim3(S_LEN / QT, B * HEADS), 256>>>(beta);
    outproj_kernel<<<dim3(CS / 128, B * S_LEN / 128), 256>>>(w_o, b_o, out);
}